// round 10
// baseline (speedup 1.0000x reference)
#include <cuda_runtime.h>
#include <cuda_bf16.h>

#define BS 2
#define NN 512
#define DD 128
#define JS 4            // j-splits in main GEMM
#define SZ (BS*NN*DD)   // 131072

typedef unsigned long long u64;

// ---------------- device scratch (no allocs allowed) ----------------
__device__ float g_sq[SZ];         // sigmoid(q)
__device__ float g_ek[SZ];         // exp(k)   (|k| <~ 5, safe unshifted)
__device__ float g_v [SZ];         // raw v
__device__ float g_eB[NN*NN];      // exp(B)
__device__ float g_pn[JS*SZ];      // partial numerators
__device__ float g_pd[JS*SZ];      // partial denominators

// ---------------- f32x2 + cp.async helpers ----------------
__device__ __forceinline__ u64 pack2(float lo, float hi) {
    u64 r; asm("mov.b64 %0, {%1, %2};" : "=l"(r) : "f"(lo), "f"(hi)); return r;
}
__device__ __forceinline__ void ffma2(u64 &acc, u64 a, u64 b) {
    asm("fma.rn.f32x2 %0, %1, %2, %0;" : "+l"(acc) : "l"(a), "l"(b));
}
__device__ __forceinline__ u64 mul2(u64 a, u64 b) {
    u64 r; asm("mul.rn.f32x2 %0, %1, %2;" : "=l"(r) : "l"(a), "l"(b)); return r;
}
__device__ __forceinline__ float2 unpack2(u64 v) {
    float lo, hi; asm("mov.b64 {%0, %1}, %2;" : "=f"(lo), "=f"(hi) : "l"(v));
    return make_float2(lo, hi);
}
__device__ __forceinline__ void cp16(void* sdst, const void* gsrc) {
    unsigned s = (unsigned)__cvta_generic_to_shared(sdst);
    asm volatile("cp.async.ca.shared.global [%0], [%1], 16;" :: "r"(s), "l"(gsrc));
}
__device__ __forceinline__ void cp4(void* sdst, const void* gsrc) {
    unsigned s = (unsigned)__cvta_generic_to_shared(sdst);
    asm volatile("cp.async.ca.shared.global [%0], [%1], 4;" :: "r"(s), "l"(gsrc));
}
__device__ __forceinline__ void cp_commit() { asm volatile("cp.async.commit_group;"); }
template<int NPEND> __device__ __forceinline__ void cp_wait() {
    asm volatile("cp.async.wait_group %0;" :: "n"(NPEND));
}

// ---------------- K1: projections (lane-per-row) + eB ----------------
// grid (32, 7), 256 threads.
//   y = 0..5: GEMM slice: mat = y>>1 (0=q,1=k,2=v), d-half = (y&1)*64.
//             CTA = 32 rows x 64 d. Warp = 32 rows x 8 d (lane = row).
//   y = 6:    g_eB = exp(B), 8192 floats per block.
__global__ __launch_bounds__(256) void proj_kernel(
    const float* __restrict__ x,
    const float* __restrict__ Wq, const float* __restrict__ bq,
    const float* __restrict__ Wk, const float* __restrict__ bk,
    const float* __restrict__ Wv, const float* __restrict__ bv,
    const float* __restrict__ Bm)
{
    __shared__ float xs[32][132];      // 32 rows x 128 c, stride 132 (aligned+spread)
    __shared__ float Ws[2][32][64];    // W c-chunk x d-half
    const int slice = blockIdx.y;
    const int tid = threadIdx.x;

    if (slice == 6) {
        #pragma unroll
        for (int r = 0; r < 8; ++r) {
            const int off = blockIdx.x * 8192 + r * 1024 + tid * 4;
            const float4 b4 = *(const float4*)&Bm[off];
            float4 e;
            e.x = __expf(b4.x); e.y = __expf(b4.y);
            e.z = __expf(b4.z); e.w = __expf(b4.w);
            *(float4*)&g_eB[off] = e;
        }
        return;
    }

    const int mat = slice >> 1;
    const int d0h = (slice & 1) * 64;
    const float* W    = (mat==0) ? Wq : ((mat==1) ? Wk : Wv);
    const float* bias = (mat==0) ? bq : ((mat==1) ? bk : bv);
    const int row0 = blockIdx.x * 32;
    const int lane = tid & 31;
    const int w    = tid >> 5;         // warp 0..7
    const int dw   = w * 8;            // d-offset within the 64-half

    // stage x tile (plain LDG/STS; visible after first barrier)
    #pragma unroll
    for (int q = 0; q < 4; ++q) {
        const int e = tid + q * 256;
        const int r = e >> 5, c4 = (e & 31) * 4;
        const float4 xv = *(const float4*)&x[(row0 + r)*128 + c4];
        xs[r][c4+0] = xv.x; xs[r][c4+1] = xv.y;
        xs[r][c4+2] = xv.z; xs[r][c4+3] = xv.w;
    }
    // stage W chunk 0 (c rows 0..31 of the d-half)
    #pragma unroll
    for (int q = 0; q < 2; ++q) {
        const int e = tid + q * 256;
        const int row = e >> 4, seg = (e & 15) * 4;
        cp16(&Ws[0][row][seg], &W[row*128 + d0h + seg]);
    }
    cp_commit();

    // 8 output floats per lane -> 4 u64 accumulators
    u64 acc[4];
    {
        const u64* bp = (const u64*)&bias[d0h + dw];
        acc[0] = bp[0]; acc[1] = bp[1]; acc[2] = bp[2]; acc[3] = bp[3];
    }

    for (int cc = 0; cc < 128; cc += 32) {
        const int s = (cc >> 5) & 1;
        if (cc + 32 < 128) {
            const int sn = s ^ 1;
            #pragma unroll
            for (int q = 0; q < 2; ++q) {
                const int e = tid + q * 256;
                const int row = e >> 4, seg = (e & 15) * 4;
                cp16(&Ws[sn][row][seg], &W[(cc + 32 + row)*128 + d0h + seg]);
            }
            cp_commit();
            cp_wait<1>();
        } else {
            cp_wait<0>();
        }
        __syncthreads();
        #pragma unroll
        for (int c = 0; c < 32; c += 4) {
            const float4 xv = *(const float4*)&xs[lane][cc + c];  // lane-distinct
            const float xf[4] = {xv.x, xv.y, xv.z, xv.w};
            #pragma unroll
            for (int t = 0; t < 4; ++t) {
                const u64 X = pack2(xf[t], xf[t]);
                const u64* wp = (const u64*)&Ws[s][c + t][dw];    // warp-uniform bcast
                ffma2(acc[0], X, wp[0]); ffma2(acc[1], X, wp[1]);
                ffma2(acc[2], X, wp[2]); ffma2(acc[3], X, wp[3]);
            }
        }
        __syncthreads();
    }

    // epilogue: 8 floats at [row0+lane][d0h+dw .. +7]
    float o[8];
    #pragma unroll
    for (int p = 0; p < 4; ++p) {
        const float2 f = unpack2(acc[p]);
        o[p*2] = f.x; o[p*2+1] = f.y;
    }
    const int off = (row0 + lane)*128 + d0h + dw;
    if (mat == 0) {
        #pragma unroll
        for (int p = 0; p < 8; ++p) o[p] = 1.f/(1.f+__expf(-o[p]));
        *(float4*)&g_sq[off] = make_float4(o[0],o[1],o[2],o[3]);
        *(float4*)&g_sq[off+4] = make_float4(o[4],o[5],o[6],o[7]);
    } else if (mat == 1) {
        #pragma unroll
        for (int p = 0; p < 8; ++p) o[p] = __expf(o[p]);
        *(float4*)&g_ek[off] = make_float4(o[0],o[1],o[2],o[3]);
        *(float4*)&g_ek[off+4] = make_float4(o[4],o[5],o[6],o[7]);
    } else {
        *(float4*)&g_v[off] = make_float4(o[0],o[1],o[2],o[3]);
        *(float4*)&g_v[off+4] = make_float4(o[4],o[5],o[6],o[7]);
    }
}

// ---------------- K2: partial GEMM  pn|pd += eB @ (ek*v | ek) ----------------
// grid (64, 4, 2): x = itile(16)*js(4), y = 32-d tile, z = batch. 128 threads.
// CTA = 32 i x 32 d x 128 j. Warp = 32 i x 8 d (lane = i).
// Per j per lane: 1 LDS.32 eB + pack2 + bcast k/v + 4 mul2 + 8 ffma2.
__global__ __launch_bounds__(128) void aft_kernel()
{
    __shared__ float eBs[2][32][33];   // [i][j-chunk], stride 33 (conflict-free lane reads)
    __shared__ float vvs[2][32][32];   // [j][d] raw v
    __shared__ float eks[2][32][32];   // [j][d] exp(k)
    const int jx  = blockIdx.x & 3;
    const int it0 = (blockIdx.x >> 2) * 32;
    const int jb  = jx * 128;
    const int d0  = blockIdx.y * 32;
    const int b   = blockIdx.z;
    const int tid = threadIdx.x;
    const int lane = tid & 31;
    const int w    = tid >> 5;
    const int dw   = w * 8;            // d-offset within the 32-d tile
    const float* vb  = g_v  + b*NN*DD + d0;
    const float* ekb = g_ek + b*NN*DD + d0;

    u64 aN[4], aD[4];
    #pragma unroll
    for (int p = 0; p < 4; ++p) { aN[p] = 0; aD[p] = 0; }

    auto stage = [&](int s, int jc) {
        // v/ek: 32 j x 32 d floats = 256 float4 each -> 2 cp16/thread each
        #pragma unroll
        for (int q = 0; q < 2; ++q) {
            const int e = tid + q*128;
            const int j = e >> 3, dd = (e & 7) * 4;
            cp16(&vvs[s][j][dd], &vb[(jb + jc + j)*DD + dd]);
            cp16(&eks[s][j][dd], &ekb[(jb + jc + j)*DD + dd]);
        }
        // eB: 32 i x 32 j floats, rows stride 33 (misaligned for cp16) -> cp4 x8
        #pragma unroll
        for (int q = 0; q < 8; ++q) {
            const int e = tid + q*128;
            const int i = e >> 5, c = e & 31;
            cp4(&eBs[s][i][c], &g_eB[(it0 + i)*NN + jb + jc + c]);
        }
    };

    stage(0, 0);
    cp_commit();

    for (int m = 0; m < 4; ++m) {
        const int s = m & 1;
        if (m + 1 < 4) { stage(s ^ 1, (m + 1)*32); cp_commit(); cp_wait<1>(); }
        else           { cp_wait<0>(); }
        __syncthreads();
        #pragma unroll 8
        for (int j = 0; j < 32; ++j) {
            const float e = eBs[s][lane][j];       // lane-distinct, 1 wf
            const u64 E = pack2(e, e);
            const u64* kp = (const u64*)&eks[s][j][dw];  // warp-uniform bcast
            const u64* vp = (const u64*)&vvs[s][j][dw];
            #pragma unroll
            for (int p = 0; p < 4; ++p) {
                const u64 k = kp[p];
                const u64 ev = mul2(k, vp[p]);
                ffma2(aN[p], E, ev);
                ffma2(aD[p], E, k);
            }
        }
        __syncthreads();
    }

    const int pbase = jx * SZ;
    const int off = (b*NN + it0 + lane)*DD + d0 + dw;
    float n[8], dn[8];
    #pragma unroll
    for (int p = 0; p < 4; ++p) {
        const float2 fn = unpack2(aN[p]); n[p*2] = fn.x; n[p*2+1] = fn.y;
        const float2 fd = unpack2(aD[p]); dn[p*2] = fd.x; dn[p*2+1] = fd.y;
    }
    *(float4*)&g_pn[pbase + off]     = make_float4(n[0],n[1],n[2],n[3]);
    *(float4*)&g_pn[pbase + off + 4] = make_float4(n[4],n[5],n[6],n[7]);
    *(float4*)&g_pd[pbase + off]     = make_float4(dn[0],dn[1],dn[2],dn[3]);
    *(float4*)&g_pd[pbase + off + 4] = make_float4(dn[4],dn[5],dn[6],dn[7]);
}

// ---------------- K3: reduce partials + epilogue ----------------
__global__ __launch_bounds__(256) void reduce_kernel(float* __restrict__ out)
{
    const int off = (blockIdx.x * 256 + threadIdx.x) * 4;
    float4 n = *(const float4*)&g_pn[off];
    float4 dn = *(const float4*)&g_pd[off];
    #pragma unroll
    for (int js = 1; js < JS; ++js) {
        const float4 a = *(const float4*)&g_pn[js*SZ + off];
        const float4 c = *(const float4*)&g_pd[js*SZ + off];
        n.x += a.x; n.y += a.y; n.z += a.z; n.w += a.w;
        dn.x += c.x; dn.y += c.y; dn.z += c.z; dn.w += c.w;
    }
    const float4 sq = *(const float4*)&g_sq[off];
    float4 o;
    o.x = sq.x * __fdividef(n.x, dn.x);
    o.y = sq.y * __fdividef(n.y, dn.y);
    o.z = sq.z * __fdividef(n.z, dn.z);
    o.w = sq.w * __fdividef(n.w, dn.w);
    *(float4*)&out[off] = o;
}

// ---------------- launch ----------------
extern "C" void kernel_launch(void* const* d_in, const int* in_sizes, int n_in,
                              void* d_out, int out_size)
{
    const float* x  = (const float*)d_in[0];
    const float* Wq = (const float*)d_in[1];
    const float* bq = (const float*)d_in[2];
    const float* Wk = (const float*)d_in[3];
    const float* bk = (const float*)d_in[4];
    const float* Wv = (const float*)d_in[5];
    const float* bv = (const float*)d_in[6];
    const float* B  = (const float*)d_in[7];
    float* out = (float*)d_out;

    proj_kernel<<<dim3(32, 7), 256>>>(x, Wq, bq, Wk, bk, Wv, bv, B);
    aft_kernel<<<dim3(64, 4, 2), 128>>>();
    reduce_kernel<<<SZ/4/256, 256>>>(out);
}

// round 12
// speedup vs baseline: 1.0574x; 1.0574x over previous
#include <cuda_runtime.h>
#include <cuda_bf16.h>
#include <cstdint>

#define BS 2
#define NN 512
#define DD 128
#define SZ (BS*NN*DD)   // 131072
#define KS 4            // K-splits in tensor GEMM

// tcgen05 is arch-SPECIFIC (sm_103a / sm_100a); the generic compute_103 PTX
// pass must compile a fallback instead.
#if defined(__CUDA_ARCH_FEAT_SM103_ALL) || defined(__CUDA_ARCH_FEAT_SM100_ALL) || defined(__CUDA_ARCH_FEAT_SM101_ALL)
#define HAS_TC 1
#else
#define HAS_TC 0
#endif

typedef unsigned long long u64;

// ---------------- device scratch (no allocs allowed) ----------------
__device__ float g_sq[SZ];                    // sigmoid(q)
__device__ float g_ek[SZ];                    // exp(k) f32
__device__ float g_v [SZ];                    // raw v f32
__device__ __nv_bfloat16 g_ah[NN*NN];         // eB hi
__device__ __nv_bfloat16 g_al[NN*NN];         // eB lo
__device__ __nv_bfloat16 g_bh[BS*256*NN];     // [b][n][j]: n<128 -> ev^T, n>=128 -> ek^T (hi)
__device__ __nv_bfloat16 g_bl[BS*256*NN];     // lo
__device__ float g_part[KS*BS*NN*256];        // MMA partials [ks][b][i][256]

// ---------------- f32x2 + cp.async helpers ----------------
__device__ __forceinline__ u64 pack2(float lo, float hi) {
    u64 r; asm("mov.b64 %0, {%1, %2};" : "=l"(r) : "f"(lo), "f"(hi)); return r;
}
__device__ __forceinline__ void ffma2(u64 &acc, u64 a, u64 b) {
    asm("fma.rn.f32x2 %0, %1, %2, %0;" : "+l"(acc) : "l"(a), "l"(b));
}
__device__ __forceinline__ float2 unpack2(u64 v) {
    float lo, hi; asm("mov.b64 {%0, %1}, %2;" : "=f"(lo), "=f"(hi) : "l"(v));
    return make_float2(lo, hi);
}
__device__ __forceinline__ void cp16(void* sdst, const void* gsrc) {
    unsigned s = (unsigned)__cvta_generic_to_shared(sdst);
    asm volatile("cp.async.ca.shared.global [%0], [%1], 16;" :: "r"(s), "l"(gsrc));
}
__device__ __forceinline__ void cp_commit() { asm volatile("cp.async.commit_group;"); }
template<int NPEND> __device__ __forceinline__ void cp_wait() {
    asm volatile("cp.async.wait_group %0;" :: "n"(NPEND));
}

// ---------------- tcgen05 helpers (guarded) ----------------
__device__ __forceinline__ uint32_t smem_u32(const void* p) {
    return (uint32_t)__cvta_generic_to_shared(p);
}
#if HAS_TC
__device__ __forceinline__ uint32_t elect_one_pred() {
    uint32_t pred;
    asm volatile("{\n\t.reg .pred p;\n\telect.sync _|p, 0xFFFFFFFF;\n\t"
                 "selp.b32 %0, 1, 0, p;\n\t}" : "=r"(pred));
    return pred;
}
// SW128 K-major descriptor: layout=2, version=1, SBO=64 (1024B), LBO=1 (16B)
static constexpr u64 DESC_BASE_SW128 =
    (u64(2) << 61) | (u64(1) << 46) | (u64(64) << 32) | (u64(1) << 16);
__device__ __forceinline__ u64 make_desc(uint32_t addr) {
    return DESC_BASE_SW128 | ((u64)(addr >> 4) & 0x3FFF);
}
__device__ __forceinline__ void mma_f16_ss(uint32_t d_tmem, u64 a_desc, u64 b_desc,
                                           uint32_t idesc, uint32_t en) {
    asm volatile(
        "{\n\t.reg .pred p;\n\tsetp.ne.u32 p, %5, 0;\n\t"
        "tcgen05.mma.cta_group::1.kind::f16 [%0], %1, %2, %3, {%4, %4, %4, %4}, p;\n\t}"
        :: "r"(d_tmem), "l"(a_desc), "l"(b_desc), "r"(idesc), "r"(0u), "r"(en)
        : "memory");
}
// idesc: F32 accum, BF16 x BF16, K-major both, M=128, N=256
static constexpr uint32_t MMA_IDESC =
    (1u << 4) | (1u << 7) | (1u << 10) | ((256u/8) << 17) | ((128u/16) << 24);
#endif

// ---------------- K1: q/k/v projections + eB bf16 hi/lo ----------------
// grid (64, 4), 256 threads. (R7 structure — best measured proj)
__global__ __launch_bounds__(256) void proj_kernel(
    const float* __restrict__ x,
    const float* __restrict__ Wq, const float* __restrict__ bq,
    const float* __restrict__ Wk, const float* __restrict__ bk,
    const float* __restrict__ Wv, const float* __restrict__ bv,
    const float* __restrict__ Bm)
{
    __shared__ float xs[16*128];
    __shared__ float Ws[2][32*128];
    const int mat = blockIdx.y;
    const int tid = threadIdx.x;

    if (mat == 3) {
        #pragma unroll
        for (int r = 0; r < 4; ++r) {
            const int off = blockIdx.x * 4096 + r * 1024 + tid * 4;
            const float4 b4 = *(const float4*)&Bm[off];
            float e[4] = {__expf(b4.x), __expf(b4.y), __expf(b4.z), __expf(b4.w)};
            __nv_bfloat16 h[4], l[4];
            #pragma unroll
            for (int t = 0; t < 4; ++t) {
                h[t] = __float2bfloat16(e[t]);
                l[t] = __float2bfloat16(e[t] - __bfloat162float(h[t]));
            }
            *(uint2*)&g_ah[off] = *(uint2*)h;
            *(uint2*)&g_al[off] = *(uint2*)l;
        }
        return;
    }

    const float* W    = (mat==0) ? Wq : ((mat==1) ? Wk : Wv);
    const float* bias = (mat==0) ? bq : ((mat==1) ? bk : bv);
    const int row0 = blockIdx.x * 16;
    const int dt = tid & 31, rt = tid >> 5;
    const int d = dt * 4;

    for (int q = tid; q < 16*128/4; q += 256) cp16(&xs[q*4], &x[row0*128 + q*4]);
    for (int q = tid; q < 32*128/4; q += 256) cp16(&Ws[0][q*4], &W[q*4]);
    cp_commit();

    const float4 bb = *(const float4*)&bias[d];
    u64 a00 = pack2(bb.x, bb.y), a01 = pack2(bb.z, bb.w);
    u64 a10 = a00, a11 = a01;

    for (int cc = 0; cc < 128; cc += 32) {
        const int s = (cc >> 5) & 1;
        if (cc + 32 < 128) {
            const int sn = s ^ 1;
            const float* Wn = &W[(cc + 32) * 128];
            for (int q = tid; q < 32*128/4; q += 256) cp16(&Ws[sn][q*4], &Wn[q*4]);
            cp_commit();
            cp_wait<1>();
        } else {
            cp_wait<0>();
        }
        __syncthreads();
        #pragma unroll
        for (int c = 0; c < 32; ++c) {
            const u64* wrow = (const u64*)&Ws[s][c*128 + d];
            const u64 w01 = wrow[0], w23 = wrow[1];
            const float x0 = xs[rt*128 + cc + c];
            const float x1 = xs[(rt+8)*128 + cc + c];
            const u64 X0 = pack2(x0, x0), X1 = pack2(x1, x1);
            ffma2(a00, X0, w01); ffma2(a01, X0, w23);
            ffma2(a10, X1, w01); ffma2(a11, X1, w23);
        }
        __syncthreads();
    }

    #pragma unroll
    for (int r = 0; r < 2; ++r) {
        const int grow = row0 + ((r == 0) ? rt : (rt + 8));
        const float2 p = unpack2(r ? a10 : a00);
        const float2 q2 = unpack2(r ? a11 : a01);
        float4 o = make_float4(p.x, p.y, q2.x, q2.y);
        if (mat == 0) {
            o.x = 1.f/(1.f+__expf(-o.x)); o.y = 1.f/(1.f+__expf(-o.y));
            o.z = 1.f/(1.f+__expf(-o.z)); o.w = 1.f/(1.f+__expf(-o.w));
            *(float4*)&g_sq[grow*128 + d] = o;
        } else if (mat == 1) {
            o.x = __expf(o.x); o.y = __expf(o.y);
            o.z = __expf(o.z); o.w = __expf(o.w);
            *(float4*)&g_ek[grow*128 + d] = o;
        } else {
            *(float4*)&g_v[grow*128 + d] = o;
        }
    }
}

// ---------------- K2: transpose + bf16 hi/lo split of ek / ev ----------------
// grid (16, 4, 2): 32-j tile, 32-d tile, batch. 256 threads.
__global__ __launch_bounds__(256) void convert_kernel()
{
    __shared__ float ekS[32][33], vS[32][33];
    const int j0 = blockIdx.x * 32;
    const int d0 = blockIdx.y * 32;
    const int b  = blockIdx.z;
    const int tid = threadIdx.x;
    const int lane = tid & 31, rw = tid >> 5;

    #pragma unroll
    for (int p = 0; p < 4; ++p) {
        const int r = rw + p*8;
        ekS[r][lane] = g_ek[(b*NN + j0 + r)*DD + d0 + lane];
        vS [r][lane] = g_v [(b*NN + j0 + r)*DD + d0 + lane];
    }
    __syncthreads();

    #pragma unroll
    for (int p = 0; p < 4; ++p) {
        const int r = rw + p*8;                 // d index within tile
        const float ek = ekS[lane][r];          // (j=j0+lane, d=d0+r)
        const float ev = ek * vS[lane][r];
        const __nv_bfloat16 evh = __float2bfloat16(ev);
        const __nv_bfloat16 evl = __float2bfloat16(ev - __bfloat162float(evh));
        const __nv_bfloat16 ekh = __float2bfloat16(ek);
        const __nv_bfloat16 ekl = __float2bfloat16(ek - __bfloat162float(ekh));
        const int offv = b*256*NN + (d0 + r)*NN + j0 + lane;        // ev rows 0..127
        const int offk = b*256*NN + (128 + d0 + r)*NN + j0 + lane;  // ek rows 128..255
        g_bh[offv] = evh; g_bl[offv] = evl;
        g_bh[offk] = ekh; g_bl[offk] = ekl;
    }
}

// ---------------- K3: tcgen05 GEMM  part = eB @ [ev|ek]  (bf16-split x3) ----------------
// grid (4 Mtile, 4 Ksplit, 2 b), 128 threads, ~194KB dynamic smem.
// A tiles: eB hi/lo [128 i][128 j] as 2 sub-tiles of [128][64j] (128B SW128 rows).
// B tiles: [ev|ek]^T hi/lo [256 n][128 j] as 2 sub-tiles of [256][64j].
#define SM_AH 1024
#define SM_AL (SM_AH + 32768)
#define SM_BH (SM_AL + 32768)
#define SM_BL (SM_BH + 65536)
#define SM_TOTAL (SM_BL + 65536 + 1024)

__global__ __launch_bounds__(128) void aft_tc_kernel()
{
    extern __shared__ char smem[];
    const int tid = threadIdx.x;
    const int wid = tid >> 5, lane = tid & 31;
    const int it0 = blockIdx.x * 128;
    const int kb  = blockIdx.y * 128;
    const int b   = blockIdx.z;

#if HAS_TC
    const uint32_t sbase = smem_u32(smem);

    // TMEM alloc (warp 0, collective), result ptr at smem[0]
    if (wid == 0) {
        asm volatile("tcgen05.alloc.cta_group::1.sync.aligned.shared::cta.b32 [%0], %1;"
                     :: "r"(sbase), "r"(256u) : "memory");
    }
    if (tid == 0) {  // mbarrier at smem[8]
        asm volatile("mbarrier.init.shared.b64 [%0], 1;" :: "r"(sbase + 8) : "memory");
    }

    // ---- stage A (hi/lo) and B (hi/lo) with SW128 swizzle ----
    {
        const __nv_bfloat16* asrc[2] = {g_ah, g_al};
        #pragma unroll
        for (int m = 0; m < 2; ++m) {
            const int abase = m ? SM_AL : SM_AH;
            #pragma unroll
            for (int sub = 0; sub < 2; ++sub) {
                #pragma unroll
                for (int q = 0; q < 8; ++q) {
                    const int e = tid + q*128;        // 0..1023
                    const int row = e >> 3, u = e & 7;
                    cp16(smem + abase + sub*16384 + row*128 + ((u ^ (row & 7)) * 16),
                         &asrc[m][(it0 + row)*NN + kb + sub*64 + u*8]);
                }
            }
        }
        const __nv_bfloat16* bsrc[2] = {g_bh, g_bl};
        #pragma unroll
        for (int m = 0; m < 2; ++m) {
            const int bbase = m ? SM_BL : SM_BH;
            #pragma unroll
            for (int sub = 0; sub < 2; ++sub) {
                #pragma unroll
                for (int q = 0; q < 16; ++q) {
                    const int e = tid + q*128;        // 0..2047
                    const int row = e >> 3, u = e & 7;
                    cp16(smem + bbase + sub*32768 + row*128 + ((u ^ (row & 7)) * 16),
                         &bsrc[m][b*256*NN + row*NN + kb + sub*64 + u*8]);
                }
            }
        }
    }
    cp_commit();
    cp_wait<0>();
    __syncthreads();
    asm volatile("fence.proxy.async.shared::cta;" ::: "memory");

    uint32_t tmem;
    asm volatile("ld.shared.b32 %0, [%1];" : "=r"(tmem) : "r"(sbase));

    // ---- MMAs: (Ah,Bh), (Ah,Bl), (Al,Bh); 2 sub-tiles x 4 K16-steps each ----
    if (wid == 0) {
        if (elect_one_pred()) {
            const u64 adh = make_desc(sbase + SM_AH);
            const u64 adl = make_desc(sbase + SM_AL);
            const u64 bdh = make_desc(sbase + SM_BH);
            const u64 bdl = make_desc(sbase + SM_BL);
            const u64 ad[3] = {adh, adh, adl};
            const u64 bd[3] = {bdh, bdl, bdh};
            int first = 1;
            #pragma unroll
            for (int sp = 0; sp < 3; ++sp) {
                #pragma unroll
                for (int sub = 0; sub < 2; ++sub) {
                    #pragma unroll
                    for (int ks = 0; ks < 4; ++ks) {
                        mma_f16_ss(tmem,
                                   ad[sp] + sub*1024 + ks*2,
                                   bd[sp] + sub*2048 + ks*2,
                                   MMA_IDESC, first ? 0u : 1u);
                        first = 0;
                    }
                }
            }
            asm volatile(
                "tcgen05.commit.cta_group::1.mbarrier::arrive::one.shared::cluster.b64 [%0];"
                :: "r"(sbase + 8) : "memory");
        }
    }
    __syncthreads();

    // wait for MMA completion
    {
        uint32_t done;
        asm volatile(
            "{\n\t.reg .pred p;\n\t"
            "mbarrier.try_wait.parity.acquire.cta.shared::cta.b64 p, [%1], 0;\n\t"
            "selp.b32 %0, 1, 0, p;\n\t}"
            : "=r"(done) : "r"(sbase + 8) : "memory");
        if (!done) {
            asm volatile(
                "{\n\t.reg .pred P1;\n\t"
                "WL_%=:\n\t"
                "mbarrier.try_wait.parity.acquire.cta.shared::cta.b64 P1, [%0], 0, 0x989680;\n\t"
                "@P1 bra.uni WD_%=;\n\t"
                "bra.uni WL_%=;\n\t"
                "WD_%=:\n\t}"
                :: "r"(sbase + 8) : "memory");
        }
    }
    asm volatile("tcgen05.fence::after_thread_sync;" ::: "memory");

    // ---- epilogue: TMEM -> gmem partials ----
    float* dst = &g_part[(((size_t)blockIdx.y*BS + b)*NN + it0 + wid*32 + lane) * 256];
    for (int cb = 0; cb < 256; cb += 32) {
        uint32_t r[32];
        asm volatile(
            "tcgen05.ld.sync.aligned.32x32b.x32.b32 "
            "{%0, %1, %2, %3, %4, %5, %6, %7, %8, %9, %10, %11, %12, %13, %14, %15, "
            " %16, %17, %18, %19, %20, %21, %22, %23, %24, %25, %26, %27, %28, %29, %30, %31}, [%32];"
            : "=r"(r[0]), "=r"(r[1]), "=r"(r[2]), "=r"(r[3]), "=r"(r[4]), "=r"(r[5]),
              "=r"(r[6]), "=r"(r[7]), "=r"(r[8]), "=r"(r[9]), "=r"(r[10]), "=r"(r[11]),
              "=r"(r[12]), "=r"(r[13]), "=r"(r[14]), "=r"(r[15]), "=r"(r[16]), "=r"(r[17]),
              "=r"(r[18]), "=r"(r[19]), "=r"(r[20]), "=r"(r[21]), "=r"(r[22]), "=r"(r[23]),
              "=r"(r[24]), "=r"(r[25]), "=r"(r[26]), "=r"(r[27]), "=r"(r[28]), "=r"(r[29]),
              "=r"(r[30]), "=r"(r[31])
            : "r"(tmem + cb));
        asm volatile("tcgen05.wait::ld.sync.aligned;" ::: "memory");
        #pragma unroll
        for (int t = 0; t < 8; ++t) {
            *(float4*)&dst[cb + t*4] = make_float4(
                __uint_as_float(r[t*4+0]), __uint_as_float(r[t*4+1]),
                __uint_as_float(r[t*4+2]), __uint_as_float(r[t*4+3]));
        }
    }

    __syncthreads();
    if (tid == 0)
        asm volatile("mbarrier.inval.shared.b64 [%0];" :: "r"(sbase + 8) : "memory");
    __syncthreads();
    if (wid == 0) {
        asm volatile("tcgen05.relinquish_alloc_permit.cta_group::1.sync.aligned;");
        asm volatile("tcgen05.dealloc.cta_group::1.sync.aligned.b32 %0, %1;"
                     :: "r"(tmem), "r"(256u));
    }
#else
    // Generic-PTX fallback (never selected at runtime on GB300: the exact
    // sm_103a cubin wins). Correct but slow scalar partial GEMM.
    (void)smem; (void)wid; (void)lane;
    const int i = it0 + tid;
    float* dst = &g_part[(((size_t)blockIdx.y*BS + b)*NN + i) * 256];
    for (int n = 0; n < 256; ++n) {
        float acc = 0.f;
        for (int j = 0; j < 128; ++j) {
            const float a = __bfloat162float(g_ah[i*NN + kb + j])
                          + __bfloat162float(g_al[i*NN + kb + j]);
            const float bb = __bfloat162float(g_bh[b*256*NN + n*NN + kb + j])
                           + __bfloat162float(g_bl[b*256*NN + n*NN + kb + j]);
            acc += a * bb;
        }
        dst[n] = acc;
    }
#endif
}

// ---------------- K4: reduce K-split partials + epilogue ----------------
__global__ __launch_bounds__(256) void reduce_kernel(float* __restrict__ out)
{
    const int idx4 = (blockIdx.x * 256 + threadIdx.x) * 4;   // 0..131068
    const int b = idx4 >> 16;
    const int i = (idx4 >> 7) & (NN - 1);
    const int d = idx4 & (DD - 1);

    float4 n = make_float4(0.f, 0.f, 0.f, 0.f);
    float4 dn = make_float4(0.f, 0.f, 0.f, 0.f);
    #pragma unroll
    for (int ks = 0; ks < KS; ++ks) {
        const float* base = &g_part[(((size_t)ks*BS + b)*NN + i) * 256];
        const float4 a = *(const float4*)&base[d];
        const float4 c = *(const float4*)&base[128 + d];
        n.x += a.x; n.y += a.y; n.z += a.z; n.w += a.w;
        dn.x += c.x; dn.y += c.y; dn.z += c.z; dn.w += c.w;
    }
    const float4 sq = *(const float4*)&g_sq[idx4];
    float4 o;
    o.x = sq.x * __fdividef(n.x, dn.x);
    o.y = sq.y * __fdividef(n.y, dn.y);
    o.z = sq.z * __fdividef(n.z, dn.z);
    o.w = sq.w * __fdividef(n.w, dn.w);
    *(float4*)&out[idx4] = o;
}

// ---------------- launch ----------------
extern "C" void kernel_launch(void* const* d_in, const int* in_sizes, int n_in,
                              void* d_out, int out_size)
{
    const float* x  = (const float*)d_in[0];
    const float* Wq = (const float*)d_in[1];
    const float* bq = (const float*)d_in[2];
    const float* Wk = (const float*)d_in[3];
    const float* bk = (const float*)d_in[4];
    const float* Wv = (const float*)d_in[5];
    const float* bv = (const float*)d_in[6];
    const float* B  = (const float*)d_in[7];
    float* out = (float*)d_out;

    cudaFuncSetAttribute(aft_tc_kernel, cudaFuncAttributeMaxDynamicSharedMemorySize, SM_TOTAL);

    proj_kernel<<<dim3(64, 4), 256>>>(x, Wq, bq, Wk, bk, Wv, bv, B);
    convert_kernel<<<dim3(16, 4, 2), 256>>>();
    aft_tc_kernel<<<dim3(4, KS, BS), 128, SM_TOTAL>>>();
    reduce_kernel<<<SZ/4/256, 256>>>(out);
}